// round 4
// baseline (speedup 1.0000x reference)
#include <cuda_runtime.h>
#include <math.h>

#define NB 8
#define NM 64
#define NA 49104
#define NC 80
#define THREADS 256
#define NA_TILES 192                 // ceil(NA / 256); last tile has 208 anchors
#define TOTB (NA_TILES * NB)         // 1536 blocks
#define NC4 (NC / 4)                 // 20 float4 per anchor

// global accumulators (zero at module load; last block resets for next replay)
__device__ double       g_cls[NB];
__device__ double       g_reg[NB];
__device__ int          g_npos[NB];
__device__ unsigned int g_done = 0;

__global__ __launch_bounds__(THREADS)
void fl_kernel(const float* __restrict__ boxes,      // [B,M,4] (x1,y1,x2,y2)
               const int*   __restrict__ labels,     // [B,M]
               const float* __restrict__ anchors,    // [1,A,4] (y1,x1,y2,x2)
               const float* __restrict__ cls,        // [B,A,C]
               const float* __restrict__ reg,        // [B,A,4]
               float*       __restrict__ out)        // [2]
{
    __shared__ float4 s_box[NM];
    __shared__ float  s_barea[NM];
    __shared__ int    s_lab[NM];
    __shared__ float  s_c[THREADS / 32];
    __shared__ float  s_r[THREADS / 32];
    __shared__ int    s_p[THREADS / 32];

    const int b     = blockIdx.y;
    const int tile  = blockIdx.x;
    const int t     = threadIdx.x;
    const int abase = tile * THREADS;

    if (t < NM) {
        float4 bx = ((const float4*)boxes)[b * NM + t];
        int lab   = labels[b * NM + t];
        if (lab == 0) {                          // degenerate: inter clamps to 0
            bx = make_float4(3e9f, 3e9f, -3e9f, -3e9f);
            s_barea[t] = 0.0f;
        } else {
            s_barea[t] = (bx.z - bx.x) * (bx.w - bx.y);
        }
        s_box[t] = bx;
        s_lab[t] = lab;
    }
    __syncthreads();

    // ---------------- phase 1: assignment (division-free argmax) ----------------
    const int a = abase + t;
    float my_reg = 0.0f, my_cls = 0.0f;
    int   my_pos = 0;

    if (a < NA) {
        float4 an = ((const float4*)anchors)[a];   // y1,x1,y2,x2
        const float ay1 = an.x, ax1 = an.y, ay2 = an.z, ax2 = an.w;
        const float a_area = (ay2 - ay1) * (ax2 - ax1);

        float best_i = -1.0f, best_u = 1.0f; int bi = 0;
        #pragma unroll 16
        for (int m = 0; m < NM; m++) {
            float4 bx = s_box[m];                  // x1,y1,x2,y2
            float iw = fminf(ax2, bx.z) - fmaxf(ax1, bx.x);
            float ih = fminf(ay2, bx.w) - fmaxf(ay1, bx.y);
            iw = fmaxf(iw, 0.0f); ih = fmaxf(ih, 0.0f);
            float inter = iw * ih;
            float ua = fmaxf(a_area + s_barea[m] - inter, 1e-8f);
            if (inter * best_u > best_i * ua) {    // strict >: first max (argmax)
                best_i = inter; best_u = ua; bi = m;
            }
        }
        float iou_max = best_i / best_u;           // one exact IEEE divide per anchor

        float4 ab = s_box[bi];
        float  bw = ab.z - ab.x, bh = ab.w - ab.y;
        bool   big = (bw * bh) > 100.0f;
        bool   pos = big ? (iou_max >= 0.5f) : (iou_max >= 0.15f);

        if (pos) {
            my_pos = 1;
            // --- regression smooth-L1 ---
            float gcx = ab.x + 0.5f * bw, gcy = ab.y + 0.5f * bh;
            float gw = fmaxf(bw, 1.0f), gh = fmaxf(bh, 1.0f);
            float aw = ax2 - ax1, ah = ay2 - ay1;
            float acx = ax1 + 0.5f * aw, acy = ay1 + 0.5f * ah;
            float tt0 = (gcy - acy) / ah;
            float tt1 = (gcx - acx) / aw;
            float tt2 = logf(gh / ah);
            float tt3 = logf(gw / aw);
            float4 r = ((const float4*)reg)[(size_t)b * NA + a];
            float d;
            d = fabsf(tt0 - r.x); my_reg += (d <= 1.0f/9.0f) ? 4.5f*d*d : d - 0.5f/9.0f;
            d = fabsf(tt1 - r.y); my_reg += (d <= 1.0f/9.0f) ? 4.5f*d*d : d - 0.5f/9.0f;
            d = fabsf(tt2 - r.z); my_reg += (d <= 1.0f/9.0f) ? 4.5f*d*d : d - 0.5f/9.0f;
            d = fabsf(tt3 - r.w); my_reg += (d <= 1.0f/9.0f) ? 4.5f*d*d : d - 0.5f/9.0f;

            // --- sparse cls correction for the target class (stream adds neg term) ---
            int al = s_lab[bi] - 1;                // in [0, NC)
            float v = cls[((size_t)b * NA + a) * NC + al];
            float p = fminf(fmaxf(v, 1e-4f), 1.0f - 1e-4f);
            float om = 1.0f - p;
            my_cls = 0.25f * om * om * (-__logf(p))       // true positive term
                   - 0.75f * p  * p  * (-__logf(om));     // minus stream's neg term
        }
    }

    // ---------------- phase 2: pure-negative focal stream over this tile ----------------
    {
        int maxa = NA - abase; if (maxa > THREADS) maxa = THREADS;
        const int nvec = maxa * NC4;
        const float4* __restrict__ cp = (const float4*)(cls + ((size_t)b * NA + abase) * NC);
        float s0 = 0.0f, s1 = 0.0f, s2 = 0.0f, s3 = 0.0f;
        #pragma unroll 5
        for (int i = t; i < nvec; i += THREADS) {
            float4 v = cp[i];
            float p0 = fminf(fmaxf(v.x, 1e-4f), 1.0f - 1e-4f);
            float p1 = fminf(fmaxf(v.y, 1e-4f), 1.0f - 1e-4f);
            float p2 = fminf(fmaxf(v.z, 1e-4f), 1.0f - 1e-4f);
            float p3 = fminf(fmaxf(v.w, 1e-4f), 1.0f - 1e-4f);
            s0 = fmaf(p0 * p0 * __logf(1.0f - p0), -0.75f, s0);
            s1 = fmaf(p1 * p1 * __logf(1.0f - p1), -0.75f, s1);
            s2 = fmaf(p2 * p2 * __logf(1.0f - p2), -0.75f, s2);
            s3 = fmaf(p3 * p3 * __logf(1.0f - p3), -0.75f, s3);
        }
        my_cls += (s0 + s1) + (s2 + s3);
    }

    // ---------------- block reduction + commit ----------------
    #pragma unroll
    for (int o = 16; o; o >>= 1) {
        my_cls += __shfl_down_sync(0xFFFFFFFFu, my_cls, o);
        my_reg += __shfl_down_sync(0xFFFFFFFFu, my_reg, o);
        my_pos += __shfl_down_sync(0xFFFFFFFFu, my_pos, o);
    }
    const int wid = t >> 5, lid = t & 31;
    if (lid == 0) { s_c[wid] = my_cls; s_r[wid] = my_reg; s_p[wid] = my_pos; }
    __syncthreads();
    if (wid == 0) {
        const int nw = THREADS / 32;
        float c = (lid < nw) ? s_c[lid] : 0.0f;
        float r = (lid < nw) ? s_r[lid] : 0.0f;
        int   p = (lid < nw) ? s_p[lid] : 0;
        #pragma unroll
        for (int o = 16; o; o >>= 1) {
            c += __shfl_down_sync(0xFFFFFFFFu, c, o);
            r += __shfl_down_sync(0xFFFFFFFFu, r, o);
            p += __shfl_down_sync(0xFFFFFFFFu, p, o);
        }
        if (lid == 0) {
            atomicAdd(&g_cls[b], (double)c);
            if (r != 0.0f) atomicAdd(&g_reg[b], (double)r);
            if (p)         atomicAdd(&g_npos[b], p);
            __threadfence();
            unsigned int ticket = atomicAdd(&g_done, 1u);
            if (ticket == (unsigned int)(TOTB - 1)) {
                // last block: finalize + reset for next graph replay
                double cs = 0.0, rs = 0.0;
                #pragma unroll
                for (int i = 0; i < NB; i++) {
                    double gc = atomicAdd(&g_cls[i], 0.0);   // atomic read
                    double gr = atomicAdd(&g_reg[i], 0.0);
                    int    np = atomicAdd(&g_npos[i], 0);
                    double den = (double)(np > 1 ? np : 1);
                    cs += gc / den;
                    rs += (np > 0) ? (gr / (4.0 * den)) : 0.0;
                    g_cls[i] = 0.0; g_reg[i] = 0.0; g_npos[i] = 0;
                }
                out[0] = (float)(cs / (double)NB);
                out[1] = (float)(rs / (double)NB * 50.0);
                __threadfence();
                g_done = 0;
            }
        }
    }
}

extern "C" void kernel_launch(void* const* d_in, const int* in_sizes, int n_in,
                              void* d_out, int out_size) {
    const float* boxes   = (const float*)d_in[0];
    const int*   labels  = (const int*)  d_in[1];
    const float* anchors = (const float*)d_in[2];
    const float* cls     = (const float*)d_in[3];
    const float* reg     = (const float*)d_in[4];
    float* out = (float*)d_out;

    dim3 grid(NA_TILES, NB);
    fl_kernel<<<grid, THREADS>>>(boxes, labels, anchors, cls, reg, out);
}